// round 9
// baseline (speedup 1.0000x reference)
#include <cuda_runtime.h>
#include <cuda_bf16.h>

#define N_ROWS 65536
#define HALF_N 32768
#define DIMS   64
#define KCODES 512
#define Q_OFF  1
#define Q_SIZE (N_ROWS * DIMS)          // 4194304
#define PERP_OFF (Q_OFF + Q_SIZE)       // 4194305
#define ENC_OFF  (PERP_OFF + 1)         // 4194306  (byte offset % 16 == 8)
#define FLT_EPS_32 1.1920929e-07f
#define TPB 224                          // 7 warps, 1 block/SM, 148 blocks, 2 rows/thread

// ---- scratch (no allocation allowed) ----
__device__ int    g_counts[KCODES];
__device__ double g_errsum;

// packed fp32x2 ops (sm_103a)
#define FMA2(acc, a, b) asm("fma.rn.f32x2 %0, %1, %2, %0;" : "+l"(acc) : "l"(a), "l"(b))
#define ADD2(out, a, b) asm("add.rn.f32x2 %0, %1, %2;" : "=l"(out) : "l"(a), "l"(b))

__device__ __forceinline__ float f2lo(unsigned long long u) { return __uint_as_float((unsigned)u); }
__device__ __forceinline__ float f2hi(unsigned long long u) { return __uint_as_float((unsigned)(u >> 32)); }

// ---------------- prep: zero accumulators only ----------------
__global__ void vq_prep() {
    int k = threadIdx.x;            // 512 threads
    if (k == 0) g_errsum = 0.0;
    g_counts[k] = 0;
}

// write quantized_st row + return sum of (q-x)^2. Row base offset ≡ 1 (mod 4):
// element j is 16B-aligned iff j%4==3. Scalars at {0,1,2,63}, float4 at 3..62.
__device__ __forceinline__ float vq_writeout(float* __restrict__ qo,
                                             const float* __restrict__ qr,
                                             const unsigned long long* __restrict__ xr) {
    float errloc = 0.0f;
#pragma unroll
    for (int jj = 0; jj < 3; jj++) {
        float xv = (jj & 1) ? f2hi(xr[jj >> 1]) : f2lo(xr[jj >> 1]);
        float d  = __fsub_rn(qr[jj], xv);
        qo[jj] = __fadd_rn(xv, d);
        errloc += __fmul_rn(d, d);
    }
    {
        float xv = f2hi(xr[31]);
        float d  = __fsub_rn(qr[63], xv);
        qo[63] = __fadd_rn(xv, d);
        errloc += __fmul_rn(d, d);
    }
#pragma unroll
    for (int i = 0; i < 15; i++) {
        int j = 3 + 4 * i;
        float x0 = f2hi(xr[(j    ) >> 1]);
        float x1 = f2lo(xr[(j + 1) >> 1]);
        float x2 = f2hi(xr[(j + 2) >> 1]);
        float x3 = f2lo(xr[(j + 3) >> 1]);
        float d0 = __fsub_rn(qr[j    ], x0);
        float d1 = __fsub_rn(qr[j + 1], x1);
        float d2 = __fsub_rn(qr[j + 2], x2);
        float d3 = __fsub_rn(qr[j + 3], x3);
        float4 o;
        o.x = __fadd_rn(x0, d0); o.y = __fadd_rn(x1, d1);
        o.z = __fadd_rn(x2, d2); o.w = __fadd_rn(x3, d3);
        *reinterpret_cast<float4*>(qo + j) = o;
        errloc += __fmul_rn(d0,d0) + __fmul_rn(d1,d1) + __fmul_rn(d2,d2) + __fmul_rn(d3,d3);
    }
    return errloc;
}

// write one-hot encodings row. Row base ≡ 2 (mod 4) floats, so eo+2 is 16B-aligned.
// Write zeros everywhere (incl. bi), then overwrite eo[bi] = 1 (same thread, ordered).
__device__ __forceinline__ void vq_enc_row(float* __restrict__ eo, int bi) {
    const float4 z4 = make_float4(0.f, 0.f, 0.f, 0.f);
    eo[0] = 0.f; eo[1] = 0.f;
    float4* p = reinterpret_cast<float4*>(eo + 2);
    for (int j4 = 0; j4 < 127; j4++) p[j4] = z4;
    eo[510] = 0.f; eo[511] = 0.f;
    eo[bi] = 1.0f;
}

// ---------------- main: wsq + argmin + quantized_st + encodings + loss + histogram ----------------
__global__ void __launch_bounds__(TPB, 1) vq_main(const float* __restrict__ x,
                                                  const float* __restrict__ w,
                                                  float* __restrict__ qout,
                                                  float* __restrict__ enc) {
    extern __shared__ float sm[];
    float* sw   = sm;                      // 32768 floats (codebook)
    float* swsq = sm + KCODES * DIMS;      // 512
    int*   shist = (int*)(sm + KCODES * DIMS + KCODES); // 512

    int tid = threadIdx.x;
    for (int i = tid; i < KCODES * DIMS / 4; i += TPB)
        ((float4*)sw)[i] = ((const float4*)w)[i];
    for (int i = tid; i < KCODES; i += TPB) shist[i] = 0;
    __syncthreads();
    // ||w_k||^2 from smem copy — identical rounding to reference (square, then sum)
    for (int k = tid; k < KCODES; k += TPB) {
        const float* wr = sw + (k << 6);
        float s = 0.0f;
        for (int d = 0; d < DIMS; d++)
            s = __fadd_rn(s, __fmul_rn(wr[d], wr[d]));
        swsq[k] = s;
    }
    __syncthreads();

    float errloc = 0.0f;
    int t = blockIdx.x * TPB + tid;
    if (t < HALF_N) {
        int rA = t, rB = t + HALF_N;
        const ulonglong2* xrowA = (const ulonglong2*)(x + (size_t)rA * DIMS);
        const ulonglong2* xrowB = (const ulonglong2*)(x + (size_t)rB * DIMS);
        unsigned long long xrA[32], xrB[32];
#pragma unroll
        for (int i = 0; i < 16; i++) { ulonglong2 u = xrowA[i]; xrA[2*i] = u.x; xrA[2*i+1] = u.y; }
#pragma unroll
        for (int i = 0; i < 16; i++) { ulonglong2 u = xrowB[i]; xrB[2*i] = u.x; xrB[2*i+1] = u.y; }

        // xsq sequentially, squares rounded individually (bit-identical to R7)
        float xsqA = 0.0f, xsqB = 0.0f;
#pragma unroll
        for (int i = 0; i < 32; i++) {
            float lo = f2lo(xrA[i]), hi = f2hi(xrA[i]);
            xsqA = __fadd_rn(xsqA, __fmul_rn(lo, lo));
            xsqA = __fadd_rn(xsqA, __fmul_rn(hi, hi));
        }
#pragma unroll
        for (int i = 0; i < 32; i++) {
            float lo = f2lo(xrB[i]), hi = f2hi(xrB[i]);
            xsqB = __fadd_rn(xsqB, __fmul_rn(lo, lo));
            xsqB = __fadd_rn(xsqB, __fmul_rn(hi, hi));
        }

        float bdA = 3.4028235e38f, bdB = 3.4028235e38f;
        int   biA = 0, biB = 0;
        for (int k = 0; k < KCODES; k++) {
            const ulonglong2* wr = (const ulonglong2*)(sw + (k << 6));
            unsigned long long aA0 = 0ull, aA1 = 0ull, aA2 = 0ull, aA3 = 0ull;
            unsigned long long aB0 = 0ull, aB1 = 0ull, aB2 = 0ull, aB3 = 0ull;
#pragma unroll
            for (int i = 0; i < 16; i += 2) {
                ulonglong2 t0 = wr[i];
                ulonglong2 t1 = wr[i + 1];
                FMA2(aA0, xrA[2*i],     t0.x);
                FMA2(aA1, xrA[2*i + 1], t0.y);
                FMA2(aA2, xrA[2*i + 2], t1.x);
                FMA2(aA3, xrA[2*i + 3], t1.y);
                FMA2(aB0, xrB[2*i],     t0.x);
                FMA2(aB1, xrB[2*i + 1], t0.y);
                FMA2(aB2, xrB[2*i + 2], t1.x);
                FMA2(aB3, xrB[2*i + 3], t1.y);
            }
            float h_k = swsq[k];
            {
                unsigned long long b0, b1, c;
                ADD2(b0, aA0, aA1);
                ADD2(b1, aA2, aA3);
                ADD2(c, b0, b1);
                float s = __fadd_rn(f2lo(c), f2hi(c));
                float hh = __fadd_rn(xsqA, h_k);
                float dist = __fmaf_rn(s, -2.0f, hh);
                if (dist < bdA) { bdA = dist; biA = k; }
            }
            {
                unsigned long long b0, b1, c;
                ADD2(b0, aB0, aB1);
                ADD2(b1, aB2, aB3);
                ADD2(c, b0, b1);
                float s = __fadd_rn(f2lo(c), f2hi(c));
                float hh = __fadd_rn(xsqB, h_k);
                float dist = __fmaf_rn(s, -2.0f, hh);
                if (dist < bdB) { bdB = dist; biB = k; }
            }
        }

        atomicAdd(&shist[biA], 1);
        atomicAdd(&shist[biB], 1);

        errloc += vq_writeout(qout + (size_t)rA * DIMS, sw + (biA << 6), xrA);
        errloc += vq_writeout(qout + (size_t)rB * DIMS, sw + (biB << 6), xrB);

        vq_enc_row(enc + (size_t)rA * KCODES, biA);
        vq_enc_row(enc + (size_t)rB * KCODES, biB);
    }
    __syncthreads();
    for (int i = tid; i < KCODES; i += TPB)
        if (shist[i]) atomicAdd(&g_counts[i], shist[i]);
#pragma unroll
    for (int o = 16; o > 0; o >>= 1) errloc += __shfl_down_sync(0xffffffffu, errloc, o);
    if ((tid & 31) == 0) atomicAdd(&g_errsum, (double)errloc);
}

// ---------------- fin: loss + perplexity ----------------
__global__ void vq_fin(float* __restrict__ out_loss, float* __restrict__ out_perp) {
    __shared__ float red[16];
    int t = threadIdx.x;                  // 512 threads
    float p = (float)g_counts[t] * (1.0f / 65536.0f);
    float v = p * __logf(p + FLT_EPS_32);
#pragma unroll
    for (int o = 16; o > 0; o >>= 1) v += __shfl_down_sync(0xffffffffu, v, o);
    if ((t & 31) == 0) red[t >> 5] = v;
    __syncthreads();
    if (t < 16) {
        float s = red[t];
#pragma unroll
        for (int o = 8; o > 0; o >>= 1) s += __shfl_down_sync(0xffffu, s, o);
        if (t == 0) {
            *out_perp = __expf(-s);
            float m = (float)(g_errsum / 4194304.0);
            *out_loss = __fadd_rn(m, __fmul_rn(0.25f, m));
        }
    }
}

extern "C" void kernel_launch(void* const* d_in, const int* in_sizes, int n_in,
                              void* d_out, int out_size) {
    const float* x = (const float*)d_in[0];
    const float* w = (const float*)d_in[1];
    if (n_in >= 2 && in_sizes[0] == KCODES * DIMS) {
        const float* t = x; x = w; w = t;
    }
    float* out  = (float*)d_out;
    float* qout = out + Q_OFF;
    float* perp = out + PERP_OFF;
    float* enc  = out + ENC_OFF;

    static bool inited = false;
    if (!inited) {   // first call = eager correctness run (not under capture)
        const int SMEM_MAIN = (KCODES * DIMS + KCODES) * 4 + KCODES * 4; // 135168
        cudaFuncSetAttribute(vq_main, cudaFuncAttributeMaxDynamicSharedMemorySize, SMEM_MAIN);
        inited = true;
    }
    const int SMEM_MAIN = (KCODES * DIMS + KCODES) * 4 + KCODES * 4;

    vq_prep<<<1, KCODES>>>();
    vq_main<<<148, TPB, SMEM_MAIN>>>(x, w, qout, enc);
    vq_fin<<<1, KCODES>>>(out, perp);
}

// round 10
// speedup vs baseline: 1.0676x; 1.0676x over previous
#include <cuda_runtime.h>
#include <cuda_bf16.h>

#define N_ROWS 65536
#define HALF_N 32768
#define DIMS   64
#define KCODES 512
#define Q_OFF  1
#define Q_SIZE (N_ROWS * DIMS)          // 4194304
#define PERP_OFF (Q_OFF + Q_SIZE)       // 4194305
#define ENC_OFF  (PERP_OFF + 1)         // 4194306  (byte offset % 16 == 8)
#define FLT_EPS_32 1.1920929e-07f
#define TPB 224                          // 7 warps, 1 block/SM, 148 blocks, 2 rows/thread
#define GRID_MAIN 148

// ---- scratch (no allocation allowed; all slots rewritten every call) ----
__device__ int   g_idx[N_ROWS];
__device__ int   g_hist[GRID_MAIN * KCODES];
__device__ float g_err[GRID_MAIN];

// packed fp32x2 ops (sm_103a)
#define FMA2(acc, a, b) asm("fma.rn.f32x2 %0, %1, %2, %0;" : "+l"(acc) : "l"(a), "l"(b))
#define ADD2(out, a, b) asm("add.rn.f32x2 %0, %1, %2;" : "=l"(out) : "l"(a), "l"(b))

__device__ __forceinline__ float f2lo(unsigned long long u) { return __uint_as_float((unsigned)u); }
__device__ __forceinline__ float f2hi(unsigned long long u) { return __uint_as_float((unsigned)(u >> 32)); }

// write quantized_st row + return sum of (q-x)^2. Row base offset ≡ 1 (mod 4):
// element j is 16B-aligned iff j%4==3. Scalars at {0,1,2,63}, float4 at 3..62.
__device__ __forceinline__ float vq_writeout(float* __restrict__ qo,
                                             const float* __restrict__ qr,
                                             const unsigned long long* __restrict__ xr) {
    float errloc = 0.0f;
#pragma unroll
    for (int jj = 0; jj < 3; jj++) {
        float xv = (jj & 1) ? f2hi(xr[jj >> 1]) : f2lo(xr[jj >> 1]);
        float d  = __fsub_rn(qr[jj], xv);
        qo[jj] = __fadd_rn(xv, d);
        errloc += __fmul_rn(d, d);
    }
    {
        float xv = f2hi(xr[31]);
        float d  = __fsub_rn(qr[63], xv);
        qo[63] = __fadd_rn(xv, d);
        errloc += __fmul_rn(d, d);
    }
#pragma unroll
    for (int i = 0; i < 15; i++) {
        int j = 3 + 4 * i;
        float x0 = f2hi(xr[(j    ) >> 1]);
        float x1 = f2lo(xr[(j + 1) >> 1]);
        float x2 = f2hi(xr[(j + 2) >> 1]);
        float x3 = f2lo(xr[(j + 3) >> 1]);
        float d0 = __fsub_rn(qr[j    ], x0);
        float d1 = __fsub_rn(qr[j + 1], x1);
        float d2 = __fsub_rn(qr[j + 2], x2);
        float d3 = __fsub_rn(qr[j + 3], x3);
        float4 o;
        o.x = __fadd_rn(x0, d0); o.y = __fadd_rn(x1, d1);
        o.z = __fadd_rn(x2, d2); o.w = __fadd_rn(x3, d3);
        *reinterpret_cast<float4*>(qo + j) = o;
        errloc += __fmul_rn(d0,d0) + __fmul_rn(d1,d1) + __fmul_rn(d2,d2) + __fmul_rn(d3,d3);
    }
    return errloc;
}

// ---------------- main: wsq + argmin + quantized_st + per-block hist/err ----------------
__global__ void __launch_bounds__(TPB, 1) vq_main(const float* __restrict__ x,
                                                  const float* __restrict__ w,
                                                  float* __restrict__ qout) {
    extern __shared__ float sm[];
    float* sw   = sm;                      // 32768 floats (codebook)
    float* swsq = sm + KCODES * DIMS;      // 512
    int*   shist = (int*)(sm + KCODES * DIMS + KCODES); // 512
    __shared__ float werr[7];

    int tid = threadIdx.x;
    for (int i = tid; i < KCODES * DIMS / 4; i += TPB)
        ((float4*)sw)[i] = ((const float4*)w)[i];
    for (int i = tid; i < KCODES; i += TPB) shist[i] = 0;
    __syncthreads();
    // ||w_k||^2 from smem copy — identical rounding to reference (square, then sum)
    for (int k = tid; k < KCODES; k += TPB) {
        const float* wr = sw + (k << 6);
        float s = 0.0f;
        for (int d = 0; d < DIMS; d++)
            s = __fadd_rn(s, __fmul_rn(wr[d], wr[d]));
        swsq[k] = s;
    }
    __syncthreads();

    float errloc = 0.0f;
    int t = blockIdx.x * TPB + tid;
    if (t < HALF_N) {
        int rA = t, rB = t + HALF_N;
        const ulonglong2* xrowA = (const ulonglong2*)(x + (size_t)rA * DIMS);
        const ulonglong2* xrowB = (const ulonglong2*)(x + (size_t)rB * DIMS);
        unsigned long long xrA[32], xrB[32];
#pragma unroll
        for (int i = 0; i < 16; i++) { ulonglong2 u = xrowA[i]; xrA[2*i] = u.x; xrA[2*i+1] = u.y; }
#pragma unroll
        for (int i = 0; i < 16; i++) { ulonglong2 u = xrowB[i]; xrB[2*i] = u.x; xrB[2*i+1] = u.y; }

        // xsq sequentially, squares rounded individually (bit-identical to R7)
        float xsqA = 0.0f, xsqB = 0.0f;
#pragma unroll
        for (int i = 0; i < 32; i++) {
            float lo = f2lo(xrA[i]), hi = f2hi(xrA[i]);
            xsqA = __fadd_rn(xsqA, __fmul_rn(lo, lo));
            xsqA = __fadd_rn(xsqA, __fmul_rn(hi, hi));
        }
#pragma unroll
        for (int i = 0; i < 32; i++) {
            float lo = f2lo(xrB[i]), hi = f2hi(xrB[i]);
            xsqB = __fadd_rn(xsqB, __fmul_rn(lo, lo));
            xsqB = __fadd_rn(xsqB, __fmul_rn(hi, hi));
        }

        float bdA = 3.4028235e38f, bdB = 3.4028235e38f;
        int   biA = 0, biB = 0;
        for (int k = 0; k < KCODES; k++) {
            const ulonglong2* wr = (const ulonglong2*)(sw + (k << 6));
            unsigned long long aA0 = 0ull, aA1 = 0ull, aA2 = 0ull, aA3 = 0ull;
            unsigned long long aB0 = 0ull, aB1 = 0ull, aB2 = 0ull, aB3 = 0ull;
#pragma unroll
            for (int i = 0; i < 16; i += 2) {
                ulonglong2 t0 = wr[i];
                ulonglong2 t1 = wr[i + 1];
                FMA2(aA0, xrA[2*i],     t0.x);
                FMA2(aA1, xrA[2*i + 1], t0.y);
                FMA2(aA2, xrA[2*i + 2], t1.x);
                FMA2(aA3, xrA[2*i + 3], t1.y);
                FMA2(aB0, xrB[2*i],     t0.x);
                FMA2(aB1, xrB[2*i + 1], t0.y);
                FMA2(aB2, xrB[2*i + 2], t1.x);
                FMA2(aB3, xrB[2*i + 3], t1.y);
            }
            float h_k = swsq[k];
            {
                unsigned long long b0, b1, c;
                ADD2(b0, aA0, aA1);
                ADD2(b1, aA2, aA3);
                ADD2(c, b0, b1);
                float s = __fadd_rn(f2lo(c), f2hi(c));
                float hh = __fadd_rn(xsqA, h_k);
                float dist = __fmaf_rn(s, -2.0f, hh);
                if (dist < bdA) { bdA = dist; biA = k; }
            }
            {
                unsigned long long b0, b1, c;
                ADD2(b0, aB0, aB1);
                ADD2(b1, aB2, aB3);
                ADD2(c, b0, b1);
                float s = __fadd_rn(f2lo(c), f2hi(c));
                float hh = __fadd_rn(xsqB, h_k);
                float dist = __fmaf_rn(s, -2.0f, hh);
                if (dist < bdB) { bdB = dist; biB = k; }
            }
        }

        g_idx[rA] = biA;
        g_idx[rB] = biB;
        atomicAdd(&shist[biA], 1);
        atomicAdd(&shist[biB], 1);

        errloc += vq_writeout(qout + (size_t)rA * DIMS, sw + (biA << 6), xrA);
        errloc += vq_writeout(qout + (size_t)rB * DIMS, sw + (biB << 6), xrB);
    }
    // per-warp err partials
#pragma unroll
    for (int o = 16; o > 0; o >>= 1) errloc += __shfl_down_sync(0xffffffffu, errloc, o);
    if ((tid & 31) == 0) werr[tid >> 5] = errloc;
    __syncthreads();
    // plain stores: no global atomics, no pre-zeroing kernel needed
    for (int i = tid; i < KCODES; i += TPB)
        g_hist[blockIdx.x * KCODES + i] = shist[i];
    if (tid == 0) {
        float s = 0.0f;
        for (int i = 0; i < 7; i++) s += werr[i];
        g_err[blockIdx.x] = s;
    }
}

// ---------------- encodings: zero-fill (side stream, overlaps vq_main), float4 body ----------------
__global__ void __launch_bounds__(256) vq_zero(float* __restrict__ enc) {
    unsigned i = blockIdx.x * 256u + threadIdx.x;   // 8,388,608 threads
    if (i < 8388607u) {
        reinterpret_cast<float4*>(enc + 2)[i] = make_float4(0.f, 0.f, 0.f, 0.f);
    } else {
        enc[0] = 0.f; enc[1] = 0.f;
        enc[33554430u] = 0.f; enc[33554431u] = 0.f;
    }
}

// ---------------- tail: scatter ones + loss + perplexity ----------------
__global__ void __launch_bounds__(512) vq_tail(float* __restrict__ enc,
                                               float* __restrict__ out_loss,
                                               float* __restrict__ out_perp) {
    int t = threadIdx.x;
    if (blockIdx.x < 128) {
        unsigned n = blockIdx.x * 512u + t;   // 65536 rows
        enc[(size_t)n * KCODES + g_idx[n]] = 1.0f;
        return;
    }
    // block 128: sum histograms + error partials, emit loss/perplexity
    __shared__ float  redv[16];
    __shared__ double rede[16];
    int cnt = 0;
#pragma unroll 4
    for (int b = 0; b < GRID_MAIN; b++) cnt += g_hist[b * KCODES + t];
    float p = (float)cnt * (1.0f / 65536.0f);
    float v = p * __logf(p + FLT_EPS_32);
    double e = (t < GRID_MAIN) ? (double)g_err[t] : 0.0;
#pragma unroll
    for (int o = 16; o > 0; o >>= 1) {
        v += __shfl_down_sync(0xffffffffu, v, o);
        e += __shfl_down_sync(0xffffffffu, e, o);
    }
    if ((t & 31) == 0) { redv[t >> 5] = v; rede[t >> 5] = e; }
    __syncthreads();
    if (t < 16) {
        float  s = redv[t];
        double d = rede[t];
#pragma unroll
        for (int o = 8; o > 0; o >>= 1) {
            s += __shfl_down_sync(0xffffu, s, o);
            d += __shfl_down_sync(0xffffu, d, o);
        }
        if (t == 0) {
            *out_perp = __expf(-s);
            float m = (float)(d / 4194304.0);
            *out_loss = __fadd_rn(m, __fmul_rn(0.25f, m));
        }
    }
}

extern "C" void kernel_launch(void* const* d_in, const int* in_sizes, int n_in,
                              void* d_out, int out_size) {
    const float* x = (const float*)d_in[0];
    const float* w = (const float*)d_in[1];
    if (n_in >= 2 && in_sizes[0] == KCODES * DIMS) {
        const float* t = x; x = w; w = t;
    }
    float* out  = (float*)d_out;
    float* qout = out + Q_OFF;
    float* perp = out + PERP_OFF;
    float* enc  = out + ENC_OFF;

    static cudaStream_t s2 = nullptr;
    static cudaEvent_t evF = nullptr, evJ = nullptr;
    static bool inited = false;
    if (!inited) {   // first call = eager correctness run (not under capture)
        cudaStreamCreateWithFlags(&s2, cudaStreamNonBlocking);
        cudaEventCreateWithFlags(&evF, cudaEventDisableTiming);
        cudaEventCreateWithFlags(&evJ, cudaEventDisableTiming);
        const int SMEM_MAIN = (KCODES * DIMS + KCODES) * 4 + KCODES * 4; // 135168
        cudaFuncSetAttribute(vq_main, cudaFuncAttributeMaxDynamicSharedMemorySize, SMEM_MAIN);
        inited = true;
    }
    const int SMEM_MAIN = (KCODES * DIMS + KCODES) * 4 + KCODES * 4;

    // fork: zero-fill encodings on side stream, overlapping vq_main
    cudaEventRecord(evF, 0);
    cudaStreamWaitEvent(s2, evF, 0);
    vq_zero<<<32768, 256, 0, s2>>>(enc);
    cudaEventRecord(evJ, s2);

    vq_main<<<GRID_MAIN, TPB, SMEM_MAIN>>>(x, w, qout);

    // join: tail needs zero-fill, g_idx, g_hist, g_err
    cudaStreamWaitEvent(0, evJ, 0);
    vq_tail<<<129, 512>>>(enc, out, perp);
}

// round 11
// speedup vs baseline: 1.1531x; 1.0801x over previous
#include <cuda_runtime.h>
#include <cuda_bf16.h>

#define N_ROWS 65536
#define HALF_N 32768
#define DIMS   64
#define KCODES 512
#define Q_OFF  1
#define Q_SIZE (N_ROWS * DIMS)          // 4194304
#define PERP_OFF (Q_OFF + Q_SIZE)       // 4194305
#define ENC_OFF  (PERP_OFF + 1)         // 4194306  (byte offset % 16 == 8)
#define FLT_EPS_32 1.1920929e-07f
#define TPB 224                          // 7 warps, 1 block/SM, 148 blocks, 2 rows/thread
#define GRID_MAIN 148

// ---- scratch (no allocation allowed; all slots rewritten every call) ----
__device__ int   g_idx[N_ROWS];
__device__ int   g_hist[GRID_MAIN * KCODES];
__device__ float g_err[GRID_MAIN];

// packed fp32x2 ops (sm_103a)
#define FMA2(acc, a, b) asm("fma.rn.f32x2 %0, %1, %2, %0;" : "+l"(acc) : "l"(a), "l"(b))
#define ADD2(out, a, b) asm("add.rn.f32x2 %0, %1, %2;" : "=l"(out) : "l"(a), "l"(b))

__device__ __forceinline__ float f2lo(unsigned long long u) { return __uint_as_float((unsigned)u); }
__device__ __forceinline__ float f2hi(unsigned long long u) { return __uint_as_float((unsigned)(u >> 32)); }

// bulk zero: smem staging -> global via TMA path (bypasses LSU/L1 store pipe)
__device__ __forceinline__ void bulk_copy(void* gdst, unsigned ssrc, int bytes) {
    asm volatile("cp.async.bulk.global.shared::cta.bulk_group [%0], [%1], %2;"
                 :: "l"(gdst), "r"(ssrc), "r"(bytes) : "memory");
}

// write quantized_st row + return sum of (q-x)^2. Row base offset ≡ 1 (mod 4):
// element j is 16B-aligned iff j%4==3. Scalars at {0,1,2,63}, float4 at 3..62.
__device__ __forceinline__ float vq_writeout(float* __restrict__ qo,
                                             const float* __restrict__ qr,
                                             const unsigned long long* __restrict__ xr) {
    float errloc = 0.0f;
#pragma unroll
    for (int jj = 0; jj < 3; jj++) {
        float xv = (jj & 1) ? f2hi(xr[jj >> 1]) : f2lo(xr[jj >> 1]);
        float d  = __fsub_rn(qr[jj], xv);
        qo[jj] = __fadd_rn(xv, d);
        errloc += __fmul_rn(d, d);
    }
    {
        float xv = f2hi(xr[31]);
        float d  = __fsub_rn(qr[63], xv);
        qo[63] = __fadd_rn(xv, d);
        errloc += __fmul_rn(d, d);
    }
#pragma unroll
    for (int i = 0; i < 15; i++) {
        int j = 3 + 4 * i;
        float x0 = f2hi(xr[(j    ) >> 1]);
        float x1 = f2lo(xr[(j + 1) >> 1]);
        float x2 = f2hi(xr[(j + 2) >> 1]);
        float x3 = f2lo(xr[(j + 3) >> 1]);
        float d0 = __fsub_rn(qr[j    ], x0);
        float d1 = __fsub_rn(qr[j + 1], x1);
        float d2 = __fsub_rn(qr[j + 2], x2);
        float d3 = __fsub_rn(qr[j + 3], x3);
        float4 o;
        o.x = __fadd_rn(x0, d0); o.y = __fadd_rn(x1, d1);
        o.z = __fadd_rn(x2, d2); o.w = __fadd_rn(x3, d3);
        *reinterpret_cast<float4*>(qo + j) = o;
        errloc += __fmul_rn(d0,d0) + __fmul_rn(d1,d1) + __fmul_rn(d2,d2) + __fmul_rn(d3,d3);
    }
    return errloc;
}

// ---------------- main: wsq + argmin + quantized_st + enc zero-fill + hist/err ----------------
__global__ void __launch_bounds__(TPB, 1) vq_main(const float* __restrict__ x,
                                                  const float* __restrict__ w,
                                                  float* __restrict__ qout,
                                                  float* __restrict__ enc) {
    extern __shared__ float sm[];
    float* sw   = sm;                      // 32768 floats (codebook)
    float* swsq = sm + KCODES * DIMS;      // 512
    int*   shist = (int*)(sm + KCODES * DIMS + KCODES); // 512
    float* zbuf = sm + KCODES * DIMS + 2 * KCODES;      // 512 floats, stays zero
    __shared__ float werr[7];

    int tid = threadIdx.x;
    for (int i = tid; i < KCODES * DIMS / 4; i += TPB)
        ((float4*)sw)[i] = ((const float4*)w)[i];
    for (int i = tid; i < KCODES; i += TPB) { shist[i] = 0; zbuf[i] = 0.0f; }
    __syncthreads();

    // ---- enc zero-fill via bulk async copies (TMA path), issued up front ----
    unsigned zsrc;
    asm("{ .reg .u64 t; cvta.to.shared.u64 t, %1; cvt.u32.u64 %0, t; }"
        : "=r"(zsrc) : "l"(zbuf));
    int t = blockIdx.x * TPB + tid;
    bool active = t < HALF_N;
    if (active) {
        int rA = t, rB = t + HALF_N;
        if (rA == 0) {
            enc[0] = 0.0f; enc[1] = 0.0f;
            bulk_copy(enc + 2, zsrc, 2032);                       // floats 2..509
        } else {
            bulk_copy(enc + (size_t)rA * KCODES - 2, zsrc, 2048); // floats rA*512-2 .. +510
        }
        bulk_copy(enc + (size_t)rB * KCODES - 2, zsrc, 2048);
        if (rB == N_ROWS - 1) {
            enc[(size_t)N_ROWS * KCODES - 2] = 0.0f;
            enc[(size_t)N_ROWS * KCODES - 1] = 0.0f;
        }
        asm volatile("cp.async.bulk.commit_group;" ::: "memory");
    }

    // ||w_k||^2 from smem copy — identical rounding to reference (square, then sum)
    for (int k = tid; k < KCODES; k += TPB) {
        const float* wr = sw + (k << 6);
        float s = 0.0f;
        for (int d = 0; d < DIMS; d++)
            s = __fadd_rn(s, __fmul_rn(wr[d], wr[d]));
        swsq[k] = s;
    }
    __syncthreads();

    float errloc = 0.0f;
    if (active) {
        int rA = t, rB = t + HALF_N;
        const ulonglong2* xrowA = (const ulonglong2*)(x + (size_t)rA * DIMS);
        const ulonglong2* xrowB = (const ulonglong2*)(x + (size_t)rB * DIMS);
        unsigned long long xrA[32], xrB[32];
#pragma unroll
        for (int i = 0; i < 16; i++) { ulonglong2 u = xrowA[i]; xrA[2*i] = u.x; xrA[2*i+1] = u.y; }
#pragma unroll
        for (int i = 0; i < 16; i++) { ulonglong2 u = xrowB[i]; xrB[2*i] = u.x; xrB[2*i+1] = u.y; }

        // xsq sequentially, squares rounded individually (bit-identical to R7)
        float xsqA = 0.0f, xsqB = 0.0f;
#pragma unroll
        for (int i = 0; i < 32; i++) {
            float lo = f2lo(xrA[i]), hi = f2hi(xrA[i]);
            xsqA = __fadd_rn(xsqA, __fmul_rn(lo, lo));
            xsqA = __fadd_rn(xsqA, __fmul_rn(hi, hi));
        }
#pragma unroll
        for (int i = 0; i < 32; i++) {
            float lo = f2lo(xrB[i]), hi = f2hi(xrB[i]);
            xsqB = __fadd_rn(xsqB, __fmul_rn(lo, lo));
            xsqB = __fadd_rn(xsqB, __fmul_rn(hi, hi));
        }

        float bdA = 3.4028235e38f, bdB = 3.4028235e38f;
        int   biA = 0, biB = 0;
        for (int k = 0; k < KCODES; k++) {
            const ulonglong2* wr = (const ulonglong2*)(sw + (k << 6));
            unsigned long long aA0 = 0ull, aA1 = 0ull, aA2 = 0ull, aA3 = 0ull;
            unsigned long long aB0 = 0ull, aB1 = 0ull, aB2 = 0ull, aB3 = 0ull;
#pragma unroll
            for (int i = 0; i < 16; i += 2) {
                ulonglong2 t0 = wr[i];
                ulonglong2 t1 = wr[i + 1];
                FMA2(aA0, xrA[2*i],     t0.x);
                FMA2(aA1, xrA[2*i + 1], t0.y);
                FMA2(aA2, xrA[2*i + 2], t1.x);
                FMA2(aA3, xrA[2*i + 3], t1.y);
                FMA2(aB0, xrB[2*i],     t0.x);
                FMA2(aB1, xrB[2*i + 1], t0.y);
                FMA2(aB2, xrB[2*i + 2], t1.x);
                FMA2(aB3, xrB[2*i + 3], t1.y);
            }
            float h_k = swsq[k];
            {
                unsigned long long b0, b1, c;
                ADD2(b0, aA0, aA1);
                ADD2(b1, aA2, aA3);
                ADD2(c, b0, b1);
                float s = __fadd_rn(f2lo(c), f2hi(c));
                float hh = __fadd_rn(xsqA, h_k);
                float dist = __fmaf_rn(s, -2.0f, hh);
                if (dist < bdA) { bdA = dist; biA = k; }
            }
            {
                unsigned long long b0, b1, c;
                ADD2(b0, aB0, aB1);
                ADD2(b1, aB2, aB3);
                ADD2(c, b0, b1);
                float s = __fadd_rn(f2lo(c), f2hi(c));
                float hh = __fadd_rn(xsqB, h_k);
                float dist = __fmaf_rn(s, -2.0f, hh);
                if (dist < bdB) { bdB = dist; biB = k; }
            }
        }

        g_idx[rA] = biA;
        g_idx[rB] = biB;
        atomicAdd(&shist[biA], 1);
        atomicAdd(&shist[biB], 1);

        errloc += vq_writeout(qout + (size_t)rA * DIMS, sw + (biA << 6), xrA);
        errloc += vq_writeout(qout + (size_t)rB * DIMS, sw + (biB << 6), xrB);
    }
    // per-warp err partials
#pragma unroll
    for (int o = 16; o > 0; o >>= 1) errloc += __shfl_down_sync(0xffffffffu, errloc, o);
    if ((tid & 31) == 0) werr[tid >> 5] = errloc;
    __syncthreads();
    // plain stores: no global atomics, no pre-zeroing kernel needed
    for (int i = tid; i < KCODES; i += TPB)
        g_hist[blockIdx.x * KCODES + i] = shist[i];
    if (tid == 0) {
        float s = 0.0f;
        for (int i = 0; i < 7; i++) s += werr[i];
        g_err[blockIdx.x] = s;
    }
    // ensure all bulk zero-fills complete before kernel end (tail scatters the 1.0s)
    if (active)
        asm volatile("cp.async.bulk.wait_group 0;" ::: "memory");
}

// ---------------- tail: scatter ones + loss + perplexity ----------------
__global__ void __launch_bounds__(512) vq_tail(float* __restrict__ enc,
                                               float* __restrict__ out_loss,
                                               float* __restrict__ out_perp) {
    int t = threadIdx.x;
    if (blockIdx.x < 128) {
        unsigned n = blockIdx.x * 512u + t;   // 65536 rows
        enc[(size_t)n * KCODES + g_idx[n]] = 1.0f;
        return;
    }
    // block 128: sum histograms + error partials, emit loss/perplexity
    __shared__ float  redv[16];
    __shared__ double rede[16];
    int cnt = 0;
#pragma unroll 4
    for (int b = 0; b < GRID_MAIN; b++) cnt += g_hist[b * KCODES + t];
    float p = (float)cnt * (1.0f / 65536.0f);
    float v = p * __logf(p + FLT_EPS_32);
    double e = (t < GRID_MAIN) ? (double)g_err[t] : 0.0;
#pragma unroll
    for (int o = 16; o > 0; o >>= 1) {
        v += __shfl_down_sync(0xffffffffu, v, o);
        e += __shfl_down_sync(0xffffffffu, e, o);
    }
    if ((t & 31) == 0) { redv[t >> 5] = v; rede[t >> 5] = e; }
    __syncthreads();
    if (t < 16) {
        float  s = redv[t];
        double d = rede[t];
#pragma unroll
        for (int o = 8; o > 0; o >>= 1) {
            s += __shfl_down_sync(0xffffu, s, o);
            d += __shfl_down_sync(0xffffu, d, o);
        }
        if (t == 0) {
            *out_perp = __expf(-s);
            float m = (float)(d / 4194304.0);
            *out_loss = __fadd_rn(m, __fmul_rn(0.25f, m));
        }
    }
}

extern "C" void kernel_launch(void* const* d_in, const int* in_sizes, int n_in,
                              void* d_out, int out_size) {
    const float* x = (const float*)d_in[0];
    const float* w = (const float*)d_in[1];
    if (n_in >= 2 && in_sizes[0] == KCODES * DIMS) {
        const float* t = x; x = w; w = t;
    }
    float* out  = (float*)d_out;
    float* qout = out + Q_OFF;
    float* perp = out + PERP_OFF;
    float* enc  = out + ENC_OFF;

    static bool inited = false;
    // smem: codebook 131072 + wsq 2048 + hist 2048 + zbuf 2048 = 137216
    const int SMEM_MAIN = (KCODES * DIMS + 3 * KCODES) * 4;
    if (!inited) {   // first call = eager correctness run (not under capture)
        cudaFuncSetAttribute(vq_main, cudaFuncAttributeMaxDynamicSharedMemorySize, SMEM_MAIN);
        inited = true;
    }

    vq_main<<<GRID_MAIN, TPB, SMEM_MAIN>>>(x, w, qout, enc);
    vq_tail<<<129, 512>>>(enc, out, perp);
}

// round 12
// speedup vs baseline: 1.2122x; 1.0513x over previous
#include <cuda_runtime.h>
#include <cuda_bf16.h>

#define N_ROWS 65536
#define HALF_N 32768
#define DIMS   64
#define KCODES 512
#define Q_OFF  1
#define Q_SIZE (N_ROWS * DIMS)          // 4194304
#define PERP_OFF (Q_OFF + Q_SIZE)       // 4194305
#define ENC_OFF  (PERP_OFF + 1)         // 4194306  (byte offset % 16 == 8)
#define FLT_EPS_32 1.1920929e-07f
#define TPB 224                          // 7 warps, 1 block/SM, 148 blocks, 2 rows/thread
#define GRID_MAIN 148

// ---- scratch (no allocation allowed) ----
// g_counts/g_errsum: zero at load; tail re-zeros after each consumption -> every
// call (eager or graph replay) starts from zero. Deterministic.
__device__ int    g_idx[N_ROWS];
__device__ int    g_counts[KCODES];
__device__ double g_errsum;

// packed fp32x2 ops (sm_103a)
#define FMA2(acc, a, b) asm("fma.rn.f32x2 %0, %1, %2, %0;" : "+l"(acc) : "l"(a), "l"(b))
#define ADD2(out, a, b) asm("add.rn.f32x2 %0, %1, %2;" : "=l"(out) : "l"(a), "l"(b))

__device__ __forceinline__ float f2lo(unsigned long long u) { return __uint_as_float((unsigned)u); }
__device__ __forceinline__ float f2hi(unsigned long long u) { return __uint_as_float((unsigned)(u >> 32)); }

// bulk zero: smem staging -> global via TMA path (bypasses LSU/L1 store pipe)
__device__ __forceinline__ void bulk_copy(void* gdst, unsigned ssrc, int bytes) {
    asm volatile("cp.async.bulk.global.shared::cta.bulk_group [%0], [%1], %2;"
                 :: "l"(gdst), "r"(ssrc), "r"(bytes) : "memory");
}

// write quantized_st row + return sum of (q-x)^2. Row base offset ≡ 1 (mod 4):
// element j is 16B-aligned iff j%4==3. Scalars at {0,1,2,63}, float4 at 3..62.
__device__ __forceinline__ float vq_writeout(float* __restrict__ qo,
                                             const float* __restrict__ qr,
                                             const unsigned long long* __restrict__ xr) {
    float errloc = 0.0f;
#pragma unroll
    for (int jj = 0; jj < 3; jj++) {
        float xv = (jj & 1) ? f2hi(xr[jj >> 1]) : f2lo(xr[jj >> 1]);
        float d  = __fsub_rn(qr[jj], xv);
        qo[jj] = __fadd_rn(xv, d);
        errloc += __fmul_rn(d, d);
    }
    {
        float xv = f2hi(xr[31]);
        float d  = __fsub_rn(qr[63], xv);
        qo[63] = __fadd_rn(xv, d);
        errloc += __fmul_rn(d, d);
    }
#pragma unroll
    for (int i = 0; i < 15; i++) {
        int j = 3 + 4 * i;
        float x0 = f2hi(xr[(j    ) >> 1]);
        float x1 = f2lo(xr[(j + 1) >> 1]);
        float x2 = f2hi(xr[(j + 2) >> 1]);
        float x3 = f2lo(xr[(j + 3) >> 1]);
        float d0 = __fsub_rn(qr[j    ], x0);
        float d1 = __fsub_rn(qr[j + 1], x1);
        float d2 = __fsub_rn(qr[j + 2], x2);
        float d3 = __fsub_rn(qr[j + 3], x3);
        float4 o;
        o.x = __fadd_rn(x0, d0); o.y = __fadd_rn(x1, d1);
        o.z = __fadd_rn(x2, d2); o.w = __fadd_rn(x3, d3);
        *reinterpret_cast<float4*>(qo + j) = o;
        errloc += __fmul_rn(d0,d0) + __fmul_rn(d1,d1) + __fmul_rn(d2,d2) + __fmul_rn(d3,d3);
    }
    return errloc;
}

// ---------------- main: wsq + argmin + quantized_st + enc zero-fill + hist/err ----------------
__global__ void __launch_bounds__(TPB, 1) vq_main(const float* __restrict__ x,
                                                  const float* __restrict__ w,
                                                  float* __restrict__ qout,
                                                  float* __restrict__ enc) {
    extern __shared__ float sm[];
    float* sw   = sm;                      // 32768 floats (codebook)
    float* swsq = sm + KCODES * DIMS;      // 512
    int*   shist = (int*)(sm + KCODES * DIMS + KCODES); // 512
    float* zbuf = sm + KCODES * DIMS + 2 * KCODES;      // 512 floats, stays zero

    int tid = threadIdx.x;
    for (int i = tid; i < KCODES * DIMS / 4; i += TPB)
        ((float4*)sw)[i] = ((const float4*)w)[i];
    for (int i = tid; i < KCODES; i += TPB) { shist[i] = 0; zbuf[i] = 0.0f; }
    __syncthreads();

    // ---- enc zero-fill via bulk async copies (TMA path), issued up front ----
    unsigned zsrc;
    asm("{ .reg .u64 t; cvta.to.shared.u64 t, %1; cvt.u32.u64 %0, t; }"
        : "=r"(zsrc) : "l"(zbuf));
    int t = blockIdx.x * TPB + tid;
    bool active = t < HALF_N;
    if (active) {
        int rA = t, rB = t + HALF_N;
        if (rA == 0) {
            enc[0] = 0.0f; enc[1] = 0.0f;
            bulk_copy(enc + 2, zsrc, 2032);                       // floats 2..509
        } else {
            bulk_copy(enc + (size_t)rA * KCODES - 2, zsrc, 2048); // floats rA*512-2 .. +510
        }
        bulk_copy(enc + (size_t)rB * KCODES - 2, zsrc, 2048);
        if (rB == N_ROWS - 1) {
            enc[(size_t)N_ROWS * KCODES - 2] = 0.0f;
            enc[(size_t)N_ROWS * KCODES - 1] = 0.0f;
        }
        asm volatile("cp.async.bulk.commit_group;" ::: "memory");
    }

    // ||w_k||^2 from smem copy — identical rounding to reference (square, then sum)
    for (int k = tid; k < KCODES; k += TPB) {
        const float* wr = sw + (k << 6);
        float s = 0.0f;
        for (int d = 0; d < DIMS; d++)
            s = __fadd_rn(s, __fmul_rn(wr[d], wr[d]));
        swsq[k] = s;
    }
    __syncthreads();

    float errloc = 0.0f;
    if (active) {
        int rA = t, rB = t + HALF_N;
        const ulonglong2* xrowA = (const ulonglong2*)(x + (size_t)rA * DIMS);
        const ulonglong2* xrowB = (const ulonglong2*)(x + (size_t)rB * DIMS);
        unsigned long long xrA[32], xrB[32];
#pragma unroll
        for (int i = 0; i < 16; i++) { ulonglong2 u = xrowA[i]; xrA[2*i] = u.x; xrA[2*i+1] = u.y; }
#pragma unroll
        for (int i = 0; i < 16; i++) { ulonglong2 u = xrowB[i]; xrB[2*i] = u.x; xrB[2*i+1] = u.y; }

        // xsq sequentially, squares rounded individually (bit-identical to R7)
        float xsqA = 0.0f, xsqB = 0.0f;
#pragma unroll
        for (int i = 0; i < 32; i++) {
            float lo = f2lo(xrA[i]), hi = f2hi(xrA[i]);
            xsqA = __fadd_rn(xsqA, __fmul_rn(lo, lo));
            xsqA = __fadd_rn(xsqA, __fmul_rn(hi, hi));
        }
#pragma unroll
        for (int i = 0; i < 32; i++) {
            float lo = f2lo(xrB[i]), hi = f2hi(xrB[i]);
            xsqB = __fadd_rn(xsqB, __fmul_rn(lo, lo));
            xsqB = __fadd_rn(xsqB, __fmul_rn(hi, hi));
        }

        float bdA = 3.4028235e38f, bdB = 3.4028235e38f;
        int   biA = 0, biB = 0;
        for (int k = 0; k < KCODES; k++) {
            const ulonglong2* wr = (const ulonglong2*)(sw + (k << 6));
            unsigned long long aA0 = 0ull, aA1 = 0ull, aA2 = 0ull, aA3 = 0ull;
            unsigned long long aB0 = 0ull, aB1 = 0ull, aB2 = 0ull, aB3 = 0ull;
#pragma unroll
            for (int i = 0; i < 16; i += 2) {
                ulonglong2 t0 = wr[i];
                ulonglong2 t1 = wr[i + 1];
                FMA2(aA0, xrA[2*i],     t0.x);
                FMA2(aA1, xrA[2*i + 1], t0.y);
                FMA2(aA2, xrA[2*i + 2], t1.x);
                FMA2(aA3, xrA[2*i + 3], t1.y);
                FMA2(aB0, xrB[2*i],     t0.x);
                FMA2(aB1, xrB[2*i + 1], t0.y);
                FMA2(aB2, xrB[2*i + 2], t1.x);
                FMA2(aB3, xrB[2*i + 3], t1.y);
            }
            float h_k = swsq[k];
            {
                unsigned long long b0, b1, c;
                ADD2(b0, aA0, aA1);
                ADD2(b1, aA2, aA3);
                ADD2(c, b0, b1);
                float s = __fadd_rn(f2lo(c), f2hi(c));
                float hh = __fadd_rn(xsqA, h_k);
                float dist = __fmaf_rn(s, -2.0f, hh);
                if (dist < bdA) { bdA = dist; biA = k; }
            }
            {
                unsigned long long b0, b1, c;
                ADD2(b0, aB0, aB1);
                ADD2(b1, aB2, aB3);
                ADD2(c, b0, b1);
                float s = __fadd_rn(f2lo(c), f2hi(c));
                float hh = __fadd_rn(xsqB, h_k);
                float dist = __fmaf_rn(s, -2.0f, hh);
                if (dist < bdB) { bdB = dist; biB = k; }
            }
        }

        g_idx[rA] = biA;
        g_idx[rB] = biB;
        atomicAdd(&shist[biA], 1);
        atomicAdd(&shist[biB], 1);

        errloc += vq_writeout(qout + (size_t)rA * DIMS, sw + (biA << 6), xrA);
        errloc += vq_writeout(qout + (size_t)rB * DIMS, sw + (biB << 6), xrB);
    }
    __syncthreads();
    // spread-address global atomics (cheap) — tail re-zeros g_counts after reading
    for (int i = tid; i < KCODES; i += TPB)
        if (shist[i]) atomicAdd(&g_counts[i], shist[i]);
#pragma unroll
    for (int o = 16; o > 0; o >>= 1) errloc += __shfl_down_sync(0xffffffffu, errloc, o);
    if ((tid & 31) == 0) atomicAdd(&g_errsum, (double)errloc);
    // ensure all bulk zero-fills complete before kernel end (tail scatters the 1.0s)
    if (active)
        asm volatile("cp.async.bulk.wait_group 0;" ::: "memory");
}

// ---------------- tail: scatter ones + loss + perplexity (+ re-zero accumulators) ----------------
__global__ void __launch_bounds__(512) vq_tail(float* __restrict__ enc,
                                               float* __restrict__ out_loss,
                                               float* __restrict__ out_perp) {
    int t = threadIdx.x;
    if (blockIdx.x < 128) {
        unsigned n = blockIdx.x * 512u + t;   // 65536 rows
        enc[(size_t)n * KCODES + g_idx[n]] = 1.0f;
        return;
    }
    // block 128: loss + perplexity from 512 counts + 1 double, then self-zero
    __shared__ float redv[16];
    int cnt = g_counts[t];
    g_counts[t] = 0;                       // re-zero for next call (replay-safe)
    float p = (float)cnt * (1.0f / 65536.0f);
    float v = p * __logf(p + FLT_EPS_32);
#pragma unroll
    for (int o = 16; o > 0; o >>= 1) v += __shfl_down_sync(0xffffffffu, v, o);
    if ((t & 31) == 0) redv[t >> 5] = v;
    __syncthreads();
    if (t < 16) {
        float s = redv[t];
#pragma unroll
        for (int o = 8; o > 0; o >>= 1) s += __shfl_down_sync(0xffffu, s, o);
        if (t == 0) {
            *out_perp = __expf(-s);
            double d = g_errsum;
            g_errsum = 0.0;               // re-zero for next call
            float m = (float)(d / 4194304.0);
            *out_loss = __fadd_rn(m, __fmul_rn(0.25f, m));
        }
    }
}

extern "C" void kernel_launch(void* const* d_in, const int* in_sizes, int n_in,
                              void* d_out, int out_size) {
    const float* x = (const float*)d_in[0];
    const float* w = (const float*)d_in[1];
    if (n_in >= 2 && in_sizes[0] == KCODES * DIMS) {
        const float* t = x; x = w; w = t;
    }
    float* out  = (float*)d_out;
    float* qout = out + Q_OFF;
    float* perp = out + PERP_OFF;
    float* enc  = out + ENC_OFF;

    static bool inited = false;
    // smem: codebook 131072 + wsq 2048 + hist 2048 + zbuf 2048 = 137216
    const int SMEM_MAIN = (KCODES * DIMS + 3 * KCODES) * 4;
    if (!inited) {   // first call = eager correctness run (not under capture)
        cudaFuncSetAttribute(vq_main, cudaFuncAttributeMaxDynamicSharedMemorySize, SMEM_MAIN);
        inited = true;
    }

    vq_main<<<GRID_MAIN, TPB, SMEM_MAIN>>>(x, w, qout, enc);
    vq_tail<<<129, 512>>>(enc, out, perp);
}